// round 13
// baseline (speedup 1.0000x reference)
#include <cuda_runtime.h>
#include <cuda_bf16.h>
#include <math.h>
#include <stdint.h>

#define TOK 131072
#define CCH 256
#define HID 1024

// fp32 (numerically sensitive)
static __device__ float g_x [(size_t)TOK * CCH];
static __device__ float g_cmb[2048 * 4096];          // bias+mask, [combo][m][n]
// bf16 (mma / attention operands)
static __device__ __nv_bfloat16 g_q [(size_t)TOK * CCH];
static __device__ __nv_bfloat16 g_kv[(size_t)TOK * 2 * CCH];
static __device__ __nv_bfloat16 g_rw[(size_t)TOK * CCH];
static __device__ __nv_bfloat16 g_aw[(size_t)TOK * CCH];
static __device__ __nv_bfloat16 g_ao[(size_t)TOK * CCH];
static __device__ __nv_bfloat16 g_l2[(size_t)TOK * CCH];
static __device__ __nv_bfloat16 g_h [(size_t)TOK * HID];
static __device__ __nv_bfloat16 g_wt[786432];
#define WT_Q   0
#define WT_KV  65536
#define WT_P   196608
#define WT_F1  262144
#define WT_F2  524288

// ---------------- helpers ------------------------------------------------------
__device__ __forceinline__ uint32_t smem_u32(const void* p) {
    uint32_t a;
    asm("{ .reg .u64 t; cvta.to.shared.u64 t, %1; cvt.u32.u64 %0, t; }" : "=r"(a) : "l"(p));
    return a;
}
__device__ __forceinline__ void cp16(uint32_t dst, const void* src) {
    asm volatile("cp.async.cg.shared.global [%0], [%1], 16;" :: "r"(dst), "l"(src));
}
__device__ __forceinline__ void cp_commit() { asm volatile("cp.async.commit_group;" ::: "memory"); }
__device__ __forceinline__ void cp_wait1()  { asm volatile("cp.async.wait_group 1;" ::: "memory"); }
__device__ __forceinline__ void cp_wait0()  { asm volatile("cp.async.wait_group 0;" ::: "memory"); }

#define LDSM4(r0, r1, r2, r3, addr) \
    asm volatile("ldmatrix.sync.aligned.m8n8.x4.shared.b16 {%0,%1,%2,%3}, [%4];" \
        : "=r"(r0), "=r"(r1), "=r"(r2), "=r"(r3) : "r"(addr))

#define MMAB(c, a, b0, b1) \
    asm volatile("mma.sync.aligned.m16n8k16.row.col.f32.bf16.bf16.f32 " \
        "{%0,%1,%2,%3}, {%4,%5,%6,%7}, {%8,%9}, {%0,%1,%2,%3};" \
        : "+f"((c)[0]), "+f"((c)[1]), "+f"((c)[2]), "+f"((c)[3]) \
        : "r"((a)[0]), "r"((a)[1]), "r"((a)[2]), "r"((a)[3]), "r"(b0), "r"(b1))

__device__ __forceinline__ int shifted_row(int t) {
    int b_ = t >> 6, n = t & 63;
    int bi = b_ >> 8, wi = b_ & 255;
    int h = ((((wi >> 4) << 3) | (n >> 3)) + 4) & 127;
    int w = ((((wi & 15) << 3) | (n & 7)) + 4) & 127;
    return (bi << 14) | (h << 7) | w;
}

// ---------------- fused weight transpose ---------------------------------------
__global__ void transpose_all(const float* __restrict__ qw, const float* __restrict__ kvw,
                              const float* __restrict__ pw, const float* __restrict__ f1w,
                              const float* __restrict__ f2w, __nv_bfloat16* __restrict__ wt) {
    __shared__ float t[32][33];
    int b = blockIdx.x;
    const float* W; __nv_bfloat16* Wt; int K, N, nx, local;
    if (b < 64)       { W = qw;  Wt = wt + WT_Q;  K = 256;  N = 256;  nx = 8;  local = b; }
    else if (b < 192) { W = kvw; Wt = wt + WT_KV; K = 256;  N = 512;  nx = 16; local = b - 64; }
    else if (b < 256) { W = pw;  Wt = wt + WT_P;  K = 256;  N = 256;  nx = 8;  local = b - 192; }
    else if (b < 512) { W = f1w; Wt = wt + WT_F1; K = 256;  N = 1024; nx = 32; local = b - 256; }
    else              { W = f2w; Wt = wt + WT_F2; K = 1024; N = 256;  nx = 8;  local = b - 512; }
    int n0 = (local % nx) << 5, k0 = (local / nx) << 5;
    int tx = threadIdx.x, ty = threadIdx.y;
    #pragma unroll
    for (int j = 0; j < 32; j += 8) t[ty + j][tx] = W[(size_t)(k0 + ty + j) * N + n0 + tx];
    __syncthreads();
    #pragma unroll
    for (int j = 0; j < 32; j += 8)
        Wt[(size_t)(n0 + ty + j) * K + k0 + tx] = __float2bfloat16(t[tx][ty + j]);
}

// ---------------- bias+mask precombine -----------------------------------------
__global__ void build_cmb(const float* __restrict__ rel, const float* __restrict__ mask,
                          float* __restrict__ cmb) {
    int combo = blockIdx.x;
    int win = combo >> 3, head = combo & 7;
    const float* mwin = mask + win * 4096;
    float* dst = cmb + (size_t)combo * 4096;
    for (int id = threadIdx.x; id < 4096; id += 256) {
        int m = id >> 6, n = id & 63;
        int idx = ((n >> 3) - (m >> 3) + 7) * 15 + ((n & 7) - (m & 7) + 7);
        dst[id] = rel[idx * 8 + head] + mwin[n * 64 + m];
    }
}

// ---------------- LayerNorms: warp per token -----------------------------------
__global__ void __launch_bounds__(256)
ln1_kernel(const float* __restrict__ ref, const float* __restrict__ adj,
           const float* __restrict__ g, const float* __restrict__ b) {
    int t = (blockIdx.x << 3) + (threadIdx.x >> 5);
    int lane = threadIdx.x & 31;
    int base = shifted_row(t) * 256 + (lane << 3);
    float4 r0 = *(const float4*)(ref + base);
    float4 r1 = *(const float4*)(ref + base + 4);
    float4 a0 = *(const float4*)(adj + base);
    float4 a1 = *(const float4*)(adj + base + 4);
    float xr[8] = {r0.x, r0.y, r0.z, r0.w, r1.x, r1.y, r1.z, r1.w};
    float xa[8] = {a0.x, a0.y, a0.z, a0.w, a1.x, a1.y, a1.z, a1.w};
    float sr = 0.f, sr2 = 0.f, sa = 0.f, sa2 = 0.f;
    #pragma unroll
    for (int i = 0; i < 8; i++) {
        sr += xr[i]; sr2 += xr[i] * xr[i];
        sa += xa[i]; sa2 += xa[i] * xa[i];
    }
    #pragma unroll
    for (int o = 16; o > 0; o >>= 1) {
        sr  += __shfl_xor_sync(~0u, sr,  o); sr2 += __shfl_xor_sync(~0u, sr2, o);
        sa  += __shfl_xor_sync(~0u, sa,  o); sa2 += __shfl_xor_sync(~0u, sa2, o);
    }
    float mr = sr * (1.f/256.f), ma = sa * (1.f/256.f);
    float rr = rsqrtf(sr2 * (1.f/256.f) - mr * mr + 1e-5f);
    float ra = rsqrtf(sa2 * (1.f/256.f) - ma * ma + 1e-5f);
    int c0 = lane << 3;
    float4 g0 = *(const float4*)(g + c0), g1 = *(const float4*)(g + c0 + 4);
    float4 b0 = *(const float4*)(b + c0), b1 = *(const float4*)(b + c0 + 4);
    float gg[8] = {g0.x, g0.y, g0.z, g0.w, g1.x, g1.y, g1.z, g1.w};
    float bb[8] = {b0.x, b0.y, b0.z, b0.w, b1.x, b1.y, b1.z, b1.w};
    __nv_bfloat162 pr[4], pa[4];
    #pragma unroll
    for (int i = 0; i < 4; i++) {
        pr[i] = __floats2bfloat162_rn((xr[2*i] - mr) * rr * gg[2*i] + bb[2*i],
                                      (xr[2*i+1] - mr) * rr * gg[2*i+1] + bb[2*i+1]);
        pa[i] = __floats2bfloat162_rn((xa[2*i] - ma) * ra * gg[2*i] + bb[2*i],
                                      (xa[2*i+1] - ma) * ra * gg[2*i+1] + bb[2*i+1]);
    }
    int o = t * 256 + c0;
    *(uint4*)&g_rw[o] = *(uint4*)pr;
    *(uint4*)&g_aw[o] = *(uint4*)pa;
}
__global__ void __launch_bounds__(256)
ln2_kernel(const float* __restrict__ g, const float* __restrict__ b) {
    int t = (blockIdx.x << 3) + (threadIdx.x >> 5);
    int lane = threadIdx.x & 31;
    int base = t * 256 + (lane << 3);
    float4 x0 = *(const float4*)(g_x + base);
    float4 x1 = *(const float4*)(g_x + base + 4);
    float xv[8] = {x0.x, x0.y, x0.z, x0.w, x1.x, x1.y, x1.z, x1.w};
    float s = 0.f, s2 = 0.f;
    #pragma unroll
    for (int i = 0; i < 8; i++) { s += xv[i]; s2 += xv[i] * xv[i]; }
    #pragma unroll
    for (int o = 16; o > 0; o >>= 1) {
        s += __shfl_xor_sync(~0u, s, o); s2 += __shfl_xor_sync(~0u, s2, o);
    }
    float m = s * (1.f/256.f);
    float r = rsqrtf(s2 * (1.f/256.f) - m * m + 1e-5f);
    int c0 = lane << 3;
    float4 g0 = *(const float4*)(g + c0), g1 = *(const float4*)(g + c0 + 4);
    float4 b0 = *(const float4*)(b + c0), b1 = *(const float4*)(b + c0 + 4);
    float gg[8] = {g0.x, g0.y, g0.z, g0.w, g1.x, g1.y, g1.z, g1.w};
    float bb[8] = {b0.x, b0.y, b0.z, b0.w, b1.x, b1.y, b1.z, b1.w};
    __nv_bfloat162 p[4];
    #pragma unroll
    for (int i = 0; i < 4; i++)
        p[i] = __floats2bfloat162_rn((xv[2*i] - m) * r * gg[2*i] + bb[2*i],
                                     (xv[2*i+1] - m) * r * gg[2*i+1] + bb[2*i+1]);
    *(uint4*)&g_l2[base] = *(uint4*)p;
}

// ---------------- bf16 mma.sync GEMM: BM=128, BN=128, BK=64, 3 stages ----------
// row = 64 bf16 = 128B stored at 144B pitch -> (r+u)%8 permutation over the
// 8 16B units => conflict-free ldmatrix, no XOR.
#define ST 3
#define TILE_B 18432            // 128 rows * 144B
#define STG_BYTES 36864
#define GEMM_SMEM (ST * STG_BYTES)   // 108 KB

__device__ __forceinline__ void gload(uint32_t sA,
        const __nv_bfloat16* Ab, const __nv_bfloat16* Bb, int K, int k0, int tid) {
    uint32_t sB = sA + TILE_B;
    #pragma unroll
    for (int i = 0; i < 4; i++) {
        int id = tid + (i << 8);          // 0..1023
        int r = id >> 3, u = id & 7;      // row 0..127, 16B unit 0..7
        uint32_t off = (uint32_t)r * 144 + (u << 4);
        cp16(sA + off, Ab + (size_t)r * K + k0 + (u << 3));
        cp16(sB + off, Bb + (size_t)r * K + k0 + (u << 3));
    }
}

// MODE 0: f32 out  1: proj scatter+residual  2: gelu->bf16  3: +extra f32
// MODE 4: bf16 out 5: bf16 out * attn scale (q)
template <int MODE>
__global__ void __launch_bounds__(256, 2)
gemm_mma(const __nv_bfloat16* __restrict__ A, const __nv_bfloat16* __restrict__ Bt,
         const float* __restrict__ bias, float* __restrict__ C,
         int K, int N, const float* __restrict__ extra) {
    extern __shared__ __align__(128) char smem[];
    uint32_t sbase = smem_u32(smem);
    int tid = threadIdx.x;
    int lane = tid & 31, wid = tid >> 5;
    int wm = wid & 3, wn = wid >> 2;
    size_t bm = (size_t)blockIdx.y << 7;
    int bn = blockIdx.x << 7;

    const __nv_bfloat16* Ab = A + bm * K;
    const __nv_bfloat16* Bb = Bt + (size_t)bn * K;
    int nch = K >> 6;

    float c[2][8][4];
    #pragma unroll
    for (int i = 0; i < 2; i++)
        #pragma unroll
        for (int j = 0; j < 8; j++)
            #pragma unroll
            for (int k = 0; k < 4; k++) c[i][j][k] = 0.f;

    for (int p = 0; p < ST - 1; p++) {
        gload(sbase + p * STG_BYTES, Ab, Bb, K, p << 6, tid);
        cp_commit();
    }

    int sc = 0, sl = ST - 1;
    for (int it = 0; it < nch; it++) {
        cp_wait1();
        __syncthreads();
        if (it + ST - 1 < nch)
            gload(sbase + sl * STG_BYTES, Ab, Bb, K, (it + ST - 1) << 6, tid);
        cp_commit();

        uint32_t sA = sbase + sc * STG_BYTES;
        uint32_t sB = sA + TILE_B;
        #pragma unroll
        for (int kc = 0; kc < 4; kc++) {
            uint32_t a[2][4], b[4][4];
            #pragma unroll
            for (int mf = 0; mf < 2; mf++) {
                int row = (wm << 5) + (mf << 4) + (lane & 7) + (((lane >> 3) & 1) << 3);
                int u = (kc << 1) + (lane >> 4);
                LDSM4(a[mf][0], a[mf][1], a[mf][2], a[mf][3],
                      sA + (uint32_t)row * 144 + (u << 4));
            }
            #pragma unroll
            for (int g = 0; g < 4; g++) {
                int row = (wn << 6) + (g << 4) + (lane & 7) + ((lane >> 4) << 3);
                int u = (kc << 1) + ((lane >> 3) & 1);
                LDSM4(b[g][0], b[g][1], b[g][2], b[g][3],
                      sB + (uint32_t)row * 144 + (u << 4));
            }
            #pragma unroll
            for (int mf = 0; mf < 2; mf++) {
                #pragma unroll
                for (int g = 0; g < 4; g++) {
                    MMAB(c[mf][2 * g],     a[mf], b[g][0], b[g][1]);
                    MMAB(c[mf][2 * g + 1], a[mf], b[g][2], b[g][3]);
                }
            }
        }
        sc++; if (sc == ST) sc = 0;
        sl++; if (sl == ST) sl = 0;
    }

    // ---- epilogue ----
    int lr4 = lane >> 2, lc = (lane & 3) << 1;
    #pragma unroll
    for (int mf = 0; mf < 2; mf++) {
        int r0 = (int)bm + (wm << 5) + (mf << 4) + lr4;
        #pragma unroll
        for (int h = 0; h < 2; h++) {
            int row = r0 + (h << 3);
            size_t drow;
            if (MODE == 1) drow = (size_t)shifted_row(row);
            else drow = (size_t)row;
            #pragma unroll
            for (int nf = 0; nf < 8; nf++) {
                int col = bn + (wn << 6) + (nf << 3) + lc;
                float vx = c[mf][nf][2 * h]     + bias[col];
                float vy = c[mf][nf][2 * h + 1] + bias[col + 1];
                if (MODE == 2) {
                    vx = 0.5f * vx * (1.f + erff(vx * 0.70710678118654752f));
                    vy = 0.5f * vy * (1.f + erff(vy * 0.70710678118654752f));
                    __nv_bfloat16* Cb = (__nv_bfloat16*)C;
                    *(__nv_bfloat162*)&Cb[drow * (size_t)N + col] =
                        __floats2bfloat162_rn(vx, vy);
                } else if (MODE == 4 || MODE == 5) {
                    if (MODE == 5) {
                        vx *= 0.17677669529663687f;
                        vy *= 0.17677669529663687f;
                    }
                    __nv_bfloat16* Cb = (__nv_bfloat16*)C;
                    *(__nv_bfloat162*)&Cb[drow * (size_t)N + col] =
                        __floats2bfloat162_rn(vx, vy);
                } else if (MODE == 1) {
                    float2 e = *(const float2*)&extra[drow * 256 + col];
                    vx += e.x; vy += e.y;
                    *(float2*)&C[drow * 256 + col] = make_float2(vx, vy);
                } else if (MODE == 3) {
                    float2 e = *(const float2*)&extra[drow * 256 + col];
                    vx += e.x; vy += e.y;
                    *(float2*)&C[drow * (size_t)N + col] = make_float2(vx, vy);
                } else {
                    *(float2*)&C[drow * (size_t)N + col] = make_float2(vx, vy);
                }
            }
        }
    }
}

// ---------------- windowed attention -------------------------------------------
__global__ void __launch_bounds__(128)
attn_kernel(const __nv_bfloat16* __restrict__ q, const __nv_bfloat16* __restrict__ kv,
            const float* __restrict__ cmb, __nv_bfloat16* __restrict__ out) {
    __shared__ float ks[64][36];
    __shared__ float vs[64][36];
    __shared__ float cmbs[4096];
    int blk = blockIdx.x;
    int b_ = blk >> 3, head = blk & 7;
    int tid = threadIdx.x;
    int n = tid >> 1, half = tid & 1;
    int t0 = b_ << 6;
    int hoff = half << 4;
    int dbase = (head << 5) + hoff;

    {
        uint32_t cb = smem_u32(cmbs);
        const float* csrc = cmb + ((size_t)(((b_ & 255) << 3) + head) << 12);
        #pragma unroll
        for (int i = 0; i < 8; i++) {
            int id = tid + (i << 7);
            cp16(cb + id * 16, csrc + id * 4);
        }
        cp_commit();
    }

    const __nv_bfloat16* kvrow = kv + (size_t)(t0 + n) * 512 + dbase;
    #pragma unroll
    for (int j = 0; j < 2; j++) {
        uint4 uk = *(const uint4*)(kvrow + 8 * j);
        uint4 uv = *(const uint4*)(kvrow + 256 + 8 * j);
        const __nv_bfloat162* pk = (const __nv_bfloat162*)&uk;
        const __nv_bfloat162* pv = (const __nv_bfloat162*)&uv;
        #pragma unroll
        for (int i = 0; i < 4; i++) {
            float2 fk = __bfloat1622float2(pk[i]);
            float2 fv = __bfloat1622float2(pv[i]);
            ks[n][hoff + 8*j + 2*i]     = fk.x;
            ks[n][hoff + 8*j + 2*i + 1] = fk.y;
            vs[n][hoff + 8*j + 2*i]     = fv.x;
            vs[n][hoff + 8*j + 2*i + 1] = fv.y;
        }
    }
    float qr[16];
    const __nv_bfloat16* qrow = q + (size_t)(t0 + n) * 256 + dbase;
    #pragma unroll
    for (int j = 0; j < 2; j++) {
        uint4 uq = *(const uint4*)(qrow + 8 * j);
        const __nv_bfloat162* pq = (const __nv_bfloat162*)&uq;
        #pragma unroll
        for (int i = 0; i < 4; i++) {
            float2 f = __bfloat1622float2(pq[i]);
            qr[8*j + 2*i] = f.x; qr[8*j + 2*i + 1] = f.y;
        }
    }
    cp_wait0();
    __syncthreads();

    float accv[16];
    #pragma unroll
    for (int d = 0; d < 16; d++) accv[d] = 0.f;
    float sum = 0.f;
    #pragma unroll 1
    for (int mt = 0; mt < 64; mt += 16) {
        float e[16];
        #pragma unroll
        for (int i = 0; i < 16; i++) {
            int m = mt + i;
            float dp = 0.f;
            #pragma unroll
            for (int j4 = 0; j4 < 4; j4++) {
                float4 kf = *(const float4*)&ks[m][hoff + 4 * j4];
                dp += qr[4*j4+0]*kf.x + qr[4*j4+1]*kf.y + qr[4*j4+2]*kf.z + qr[4*j4+3]*kf.w;
            }
            float dot = dp + __shfl_xor_sync(~0u, dp, 1);
            e[i] = __expf(dot + cmbs[(m << 6) + n]);
        }
        #pragma unroll
        for (int i = 0; i < 16; i++) {
            int m = mt + i;
            sum += e[i];
            #pragma unroll
            for (int j4 = 0; j4 < 4; j4++) {
                float4 vf = *(const float4*)&vs[m][hoff + 4 * j4];
                accv[4*j4+0] += e[i] * vf.x; accv[4*j4+1] += e[i] * vf.y;
                accv[4*j4+2] += e[i] * vf.z; accv[4*j4+3] += e[i] * vf.w;
            }
        }
    }
    float inv = 1.f / sum;
    __nv_bfloat16* orow = out + (size_t)(t0 + n) * 256 + dbase;
    #pragma unroll
    for (int i = 0; i < 8; i++)
        *(__nv_bfloat162*)&orow[2 * i] =
            __floats2bfloat162_rn(accv[2*i] * inv, accv[2*i+1] * inv);
}

// ---------------- launch -------------------------------------------------------
extern "C" void kernel_launch(void* const* d_in, const int* in_sizes, int n_in,
                              void* d_out, int out_size) {
    (void)in_sizes; (void)n_in; (void)out_size;
    const float* ref  = (const float*)d_in[0];
    const float* adj  = (const float*)d_in[1];
    const float* mask = (const float*)d_in[2];
    const float* n1g = (const float*)d_in[5];
    const float* n1b = (const float*)d_in[6];
    const float* qw  = (const float*)d_in[7];
    const float* qb  = (const float*)d_in[8];
    const float* kvw = (const float*)d_in[9];
    const float* kvb = (const float*)d_in[10];
    const float* rel = (const float*)d_in[11];
    const float* pw  = (const float*)d_in[12];
    const float* pb  = (const float*)d_in[13];
    const float* n2g = (const float*)d_in[14];
    const float* n2b = (const float*)d_in[15];
    const float* f1w = (const float*)d_in[16];
    const float* f1b = (const float*)d_in[17];
    const float* f2w = (const float*)d_in[18];
    const float* f2b = (const float*)d_in[19];
    float* out = (float*)d_out;

    float *x, *cmb;
    __nv_bfloat16 *q, *kv, *rw, *aw, *ao, *l2, *h, *wt;
    cudaGetSymbolAddress((void**)&x,   g_x);
    cudaGetSymbolAddress((void**)&cmb, g_cmb);
    cudaGetSymbolAddress((void**)&q,   g_q);
    cudaGetSymbolAddress((void**)&kv,  g_kv);
    cudaGetSymbolAddress((void**)&rw,  g_rw);
    cudaGetSymbolAddress((void**)&aw,  g_aw);
    cudaGetSymbolAddress((void**)&ao,  g_ao);
    cudaGetSymbolAddress((void**)&l2,  g_l2);
    cudaGetSymbolAddress((void**)&h,   g_h);
    cudaGetSymbolAddress((void**)&wt,  g_wt);

    cudaFuncSetAttribute(gemm_mma<1>, cudaFuncAttributeMaxDynamicSharedMemorySize, GEMM_SMEM);
    cudaFuncSetAttribute(gemm_mma<2>, cudaFuncAttributeMaxDynamicSharedMemorySize, GEMM_SMEM);
    cudaFuncSetAttribute(gemm_mma<3>, cudaFuncAttributeMaxDynamicSharedMemorySize, GEMM_SMEM);
    cudaFuncSetAttribute(gemm_mma<4>, cudaFuncAttributeMaxDynamicSharedMemorySize, GEMM_SMEM);
    cudaFuncSetAttribute(gemm_mma<5>, cudaFuncAttributeMaxDynamicSharedMemorySize, GEMM_SMEM);

    transpose_all<<<768, dim3(32, 8)>>>(qw, kvw, pw, f1w, f2w, wt);
    build_cmb<<<2048, 256>>>(rel, mask, cmb);
    ln1_kernel<<<TOK / 8, 256>>>(ref, adj, n1g, n1b);
    gemm_mma<5><<<dim3(2, 1024), 256, GEMM_SMEM>>>(rw, wt + WT_Q,  qb,  (float*)q,  256, 256,  nullptr);
    gemm_mma<4><<<dim3(4, 1024), 256, GEMM_SMEM>>>(aw, wt + WT_KV, kvb, (float*)kv, 256, 512,  nullptr);
    attn_kernel<<<16384, 128>>>(q, kv, cmb, ao);
    gemm_mma<1><<<dim3(2, 1024), 256, GEMM_SMEM>>>(ao, wt + WT_P,  pb,  x,  256, 256,  ref);
    ln2_kernel<<<TOK / 8, 256>>>(n2g, n2b);
    gemm_mma<2><<<dim3(8, 1024), 256, GEMM_SMEM>>>(l2, wt + WT_F1, f1b, (float*)h, 256, 1024, nullptr);
    gemm_mma<3><<<dim3(2, 1024), 256, GEMM_SMEM>>>(h,  wt + WT_F2, f2b, out, 1024, 256, x);
}

// round 14
// speedup vs baseline: 1.4856x; 1.4856x over previous
#include <cuda_runtime.h>
#include <cuda_bf16.h>
#include <math.h>
#include <stdint.h>

#define TOK 131072
#define CCH 256
#define HID 1024

// fp32 (numerically sensitive)
static __device__ float g_x [(size_t)TOK * CCH];
static __device__ float g_cmb[2048 * 4096];          // bias+mask, [combo][m][n]
// bf16 (mma / attention operands)
static __device__ __nv_bfloat16 g_q [(size_t)TOK * CCH];
static __device__ __nv_bfloat16 g_kv[(size_t)TOK * 2 * CCH];
static __device__ __nv_bfloat16 g_rw[(size_t)TOK * CCH];
static __device__ __nv_bfloat16 g_aw[(size_t)TOK * CCH];
static __device__ __nv_bfloat16 g_ao[(size_t)TOK * CCH];
static __device__ __nv_bfloat16 g_l2[(size_t)TOK * CCH];
static __device__ __nv_bfloat16 g_h [(size_t)TOK * HID];
static __device__ __nv_bfloat16 g_wt[786432];
#define WT_Q   0
#define WT_KV  65536
#define WT_P   196608
#define WT_F1  262144
#define WT_F2  524288

// ---------------- helpers ------------------------------------------------------
__device__ __forceinline__ uint32_t smem_u32(const void* p) {
    uint32_t a;
    asm("{ .reg .u64 t; cvta.to.shared.u64 t, %1; cvt.u32.u64 %0, t; }" : "=r"(a) : "l"(p));
    return a;
}
__device__ __forceinline__ void cp16(uint32_t dst, const void* src) {
    asm volatile("cp.async.cg.shared.global [%0], [%1], 16;" :: "r"(dst), "l"(src));
}
__device__ __forceinline__ void cp_commit() { asm volatile("cp.async.commit_group;" ::: "memory"); }
__device__ __forceinline__ void cp_wait3()  { asm volatile("cp.async.wait_group 3;" ::: "memory"); }
__device__ __forceinline__ void cp_wait0()  { asm volatile("cp.async.wait_group 0;" ::: "memory"); }

#define LDSM4(r0, r1, r2, r3, addr) \
    asm volatile("ldmatrix.sync.aligned.m8n8.x4.shared.b16 {%0,%1,%2,%3}, [%4];" \
        : "=r"(r0), "=r"(r1), "=r"(r2), "=r"(r3) : "r"(addr))

#define MMAB(c, a, b0, b1) \
    asm volatile("mma.sync.aligned.m16n8k16.row.col.f32.bf16.bf16.f32 " \
        "{%0,%1,%2,%3}, {%4,%5,%6,%7}, {%8,%9}, {%0,%1,%2,%3};" \
        : "+f"((c)[0]), "+f"((c)[1]), "+f"((c)[2]), "+f"((c)[3]) \
        : "r"((a)[0]), "r"((a)[1]), "r"((a)[2]), "r"((a)[3]), "r"(b0), "r"(b1))

__device__ __forceinline__ int shifted_row(int t) {
    int b_ = t >> 6, n = t & 63;
    int bi = b_ >> 8, wi = b_ & 255;
    int h = ((((wi >> 4) << 3) | (n >> 3)) + 4) & 127;
    int w = ((((wi & 15) << 3) | (n & 7)) + 4) & 127;
    return (bi << 14) | (h << 7) | w;
}

// ---------------- fused prep: weight transpose + bias/mask precombine ----------
__global__ void prep_kernel(const float* __restrict__ qw, const float* __restrict__ kvw,
                            const float* __restrict__ pw, const float* __restrict__ f1w,
                            const float* __restrict__ f2w, __nv_bfloat16* __restrict__ wt,
                            const float* __restrict__ rel, const float* __restrict__ mask,
                            float* __restrict__ cmb) {
    int b = blockIdx.x;
    if (b >= 768) {
        // bias+mask combine: blocks 768..2815 -> combo 0..2047
        int combo = b - 768;
        int win = combo >> 3, head = combo & 7;
        const float* mwin = mask + win * 4096;
        float* dst = cmb + (size_t)combo * 4096;
        int tid = threadIdx.y * 32 + threadIdx.x;
        for (int id = tid; id < 4096; id += 256) {
            int m = id >> 6, n = id & 63;
            int idx = ((n >> 3) - (m >> 3) + 7) * 15 + ((n & 7) - (m & 7) + 7);
            dst[id] = rel[idx * 8 + head] + mwin[n * 64 + m];
        }
        return;
    }
    __shared__ float t[32][33];
    const float* W; __nv_bfloat16* Wt; int K, N, nx, local;
    if (b < 64)       { W = qw;  Wt = wt + WT_Q;  K = 256;  N = 256;  nx = 8;  local = b; }
    else if (b < 192) { W = kvw; Wt = wt + WT_KV; K = 256;  N = 512;  nx = 16; local = b - 64; }
    else if (b < 256) { W = pw;  Wt = wt + WT_P;  K = 256;  N = 256;  nx = 8;  local = b - 192; }
    else if (b < 512) { W = f1w; Wt = wt + WT_F1; K = 256;  N = 1024; nx = 32; local = b - 256; }
    else              { W = f2w; Wt = wt + WT_F2; K = 1024; N = 256;  nx = 8;  local = b - 512; }
    int n0 = (local % nx) << 5, k0 = (local / nx) << 5;
    int tx = threadIdx.x, ty = threadIdx.y;
    #pragma unroll
    for (int j = 0; j < 32; j += 8) t[ty + j][tx] = W[(size_t)(k0 + ty + j) * N + n0 + tx];
    __syncthreads();
    #pragma unroll
    for (int j = 0; j < 32; j += 8)
        Wt[(size_t)(n0 + ty + j) * K + k0 + tx] = __float2bfloat16(t[tx][ty + j]);
}

// ---------------- LayerNorms: warp per token -----------------------------------
__global__ void __launch_bounds__(256)
ln1_kernel(const float* __restrict__ ref, const float* __restrict__ adj,
           const float* __restrict__ g, const float* __restrict__ b) {
    int t = (blockIdx.x << 3) + (threadIdx.x >> 5);
    int lane = threadIdx.x & 31;
    int base = shifted_row(t) * 256 + (lane << 3);
    float4 r0 = *(const float4*)(ref + base);
    float4 r1 = *(const float4*)(ref + base + 4);
    float4 a0 = *(const float4*)(adj + base);
    float4 a1 = *(const float4*)(adj + base + 4);
    float xr[8] = {r0.x, r0.y, r0.z, r0.w, r1.x, r1.y, r1.z, r1.w};
    float xa[8] = {a0.x, a0.y, a0.z, a0.w, a1.x, a1.y, a1.z, a1.w};
    float sr = 0.f, sr2 = 0.f, sa = 0.f, sa2 = 0.f;
    #pragma unroll
    for (int i = 0; i < 8; i++) {
        sr += xr[i]; sr2 += xr[i] * xr[i];
        sa += xa[i]; sa2 += xa[i] * xa[i];
    }
    #pragma unroll
    for (int o = 16; o > 0; o >>= 1) {
        sr  += __shfl_xor_sync(~0u, sr,  o); sr2 += __shfl_xor_sync(~0u, sr2, o);
        sa  += __shfl_xor_sync(~0u, sa,  o); sa2 += __shfl_xor_sync(~0u, sa2, o);
    }
    float mr = sr * (1.f/256.f), ma = sa * (1.f/256.f);
    float rr = rsqrtf(sr2 * (1.f/256.f) - mr * mr + 1e-5f);
    float ra = rsqrtf(sa2 * (1.f/256.f) - ma * ma + 1e-5f);
    int c0 = lane << 3;
    float4 g0 = *(const float4*)(g + c0), g1 = *(const float4*)(g + c0 + 4);
    float4 b0 = *(const float4*)(b + c0), b1 = *(const float4*)(b + c0 + 4);
    float gg[8] = {g0.x, g0.y, g0.z, g0.w, g1.x, g1.y, g1.z, g1.w};
    float bb[8] = {b0.x, b0.y, b0.z, b0.w, b1.x, b1.y, b1.z, b1.w};
    __nv_bfloat162 pr[4], pa[4];
    #pragma unroll
    for (int i = 0; i < 4; i++) {
        pr[i] = __floats2bfloat162_rn((xr[2*i] - mr) * rr * gg[2*i] + bb[2*i],
                                      (xr[2*i+1] - mr) * rr * gg[2*i+1] + bb[2*i+1]);
        pa[i] = __floats2bfloat162_rn((xa[2*i] - ma) * ra * gg[2*i] + bb[2*i],
                                      (xa[2*i+1] - ma) * ra * gg[2*i+1] + bb[2*i+1]);
    }
    int o = t * 256 + c0;
    *(uint4*)&g_rw[o] = *(uint4*)pr;
    *(uint4*)&g_aw[o] = *(uint4*)pa;
}
__global__ void __launch_bounds__(256)
ln2_kernel(const float* __restrict__ g, const float* __restrict__ b) {
    int t = (blockIdx.x << 3) + (threadIdx.x >> 5);
    int lane = threadIdx.x & 31;
    int base = t * 256 + (lane << 3);
    float4 x0 = *(const float4*)(g_x + base);
    float4 x1 = *(const float4*)(g_x + base + 4);
    float xv[8] = {x0.x, x0.y, x0.z, x0.w, x1.x, x1.y, x1.z, x1.w};
    float s = 0.f, s2 = 0.f;
    #pragma unroll
    for (int i = 0; i < 8; i++) { s += xv[i]; s2 += xv[i] * xv[i]; }
    #pragma unroll
    for (int o = 16; o > 0; o >>= 1) {
        s += __shfl_xor_sync(~0u, s, o); s2 += __shfl_xor_sync(~0u, s2, o);
    }
    float m = s * (1.f/256.f);
    float r = rsqrtf(s2 * (1.f/256.f) - m * m + 1e-5f);
    int c0 = lane << 3;
    float4 g0 = *(const float4*)(g + c0), g1 = *(const float4*)(g + c0 + 4);
    float4 b0 = *(const float4*)(b + c0), b1 = *(const float4*)(b + c0 + 4);
    float gg[8] = {g0.x, g0.y, g0.z, g0.w, g1.x, g1.y, g1.z, g1.w};
    float bb[8] = {b0.x, b0.y, b0.z, b0.w, b1.x, b1.y, b1.z, b1.w};
    __nv_bfloat162 p[4];
    #pragma unroll
    for (int i = 0; i < 4; i++)
        p[i] = __floats2bfloat162_rn((xv[2*i] - m) * r * gg[2*i] + bb[2*i],
                                     (xv[2*i+1] - m) * r * gg[2*i+1] + bb[2*i+1]);
    *(uint4*)&g_l2[base] = *(uint4*)p;
}

// ---------------- bf16 mma.sync GEMM: BM=128, BN=128, BK=32, 5 stages ----------
// row = 32 bf16 = 64B stored at 80B pitch -> (5r+u)%8 permutation => conflict-free.
#define ST 5
#define TILE_B 10240
#define STG_BYTES 20480
#define GEMM_SMEM (ST * STG_BYTES)   // 100 KB

__device__ __forceinline__ void gload(uint32_t sA,
        const __nv_bfloat16* Ab, const __nv_bfloat16* Bb, int K, int k0, int tid) {
    uint32_t sB = sA + TILE_B;
    #pragma unroll
    for (int i = 0; i < 2; i++) {
        int id = tid + (i << 8);
        int r = id >> 2, u = id & 3;
        uint32_t off = (uint32_t)r * 80 + (u << 4);
        cp16(sA + off, Ab + (size_t)r * K + k0 + (u << 3));
        cp16(sB + off, Bb + (size_t)r * K + k0 + (u << 3));
    }
}

// MODE 0: f32 out  1: proj scatter+residual  2: gelu->bf16  3: +extra f32
// MODE 4: bf16 out 5: bf16 out * attn scale (q)
template <int MODE>
__global__ void __launch_bounds__(256, 2)
gemm_mma(const __nv_bfloat16* __restrict__ A, const __nv_bfloat16* __restrict__ Bt,
         const float* __restrict__ bias, float* __restrict__ C,
         int K, int N, const float* __restrict__ extra) {
    extern __shared__ __align__(128) char smem[];
    uint32_t sbase = smem_u32(smem);
    int tid = threadIdx.x;
    int lane = tid & 31, wid = tid >> 5;
    int wm = wid & 3, wn = wid >> 2;
    size_t bm = (size_t)blockIdx.y << 7;
    int bn = blockIdx.x << 7;

    const __nv_bfloat16* Ab = A + bm * K;
    const __nv_bfloat16* Bb = Bt + (size_t)bn * K;
    int nch = K >> 5;

    float c[2][8][4];
    #pragma unroll
    for (int i = 0; i < 2; i++)
        #pragma unroll
        for (int j = 0; j < 8; j++)
            #pragma unroll
            for (int k = 0; k < 4; k++) c[i][j][k] = 0.f;

    for (int p = 0; p < ST - 1; p++) {
        gload(sbase + p * STG_BYTES, Ab, Bb, K, p << 5, tid);
        cp_commit();
    }

    int sc = 0, sl = ST - 1;
    for (int it = 0; it < nch; it++) {
        cp_wait3();
        __syncthreads();
        if (it + ST - 1 < nch)
            gload(sbase + sl * STG_BYTES, Ab, Bb, K, (it + ST - 1) << 5, tid);
        cp_commit();

        uint32_t sA = sbase + sc * STG_BYTES;
        uint32_t sB = sA + TILE_B;
        #pragma unroll
        for (int kc = 0; kc < 2; kc++) {
            uint32_t a[2][4], b[4][4];
            #pragma unroll
            for (int mf = 0; mf < 2; mf++) {
                int row = (wm << 5) + (mf << 4) + (lane & 7) + (((lane >> 3) & 1) << 3);
                int u = (kc << 1) + (lane >> 4);
                LDSM4(a[mf][0], a[mf][1], a[mf][2], a[mf][3],
                      sA + (uint32_t)row * 80 + (u << 4));
            }
            #pragma unroll
            for (int g = 0; g < 4; g++) {
                int row = (wn << 6) + (g << 4) + (lane & 7) + ((lane >> 4) << 3);
                int u = (kc << 1) + ((lane >> 3) & 1);
                LDSM4(b[g][0], b[g][1], b[g][2], b[g][3],
                      sB + (uint32_t)row * 80 + (u << 4));
            }
            #pragma unroll
            for (int mf = 0; mf < 2; mf++) {
                #pragma unroll
                for (int g = 0; g < 4; g++) {
                    MMAB(c[mf][2 * g],     a[mf], b[g][0], b[g][1]);
                    MMAB(c[mf][2 * g + 1], a[mf], b[g][2], b[g][3]);
                }
            }
        }
        sc++; if (sc == ST) sc = 0;
        sl++; if (sl == ST) sl = 0;
    }

    // ---- epilogue ----
    int lr4 = lane >> 2, lc = (lane & 3) << 1;
    #pragma unroll
    for (int mf = 0; mf < 2; mf++) {
        int r0 = (int)bm + (wm << 5) + (mf << 4) + lr4;
        #pragma unroll
        for (int h = 0; h < 2; h++) {
            int row = r0 + (h << 3);
            size_t drow;
            if (MODE == 1) drow = (size_t)shifted_row(row);
            else drow = (size_t)row;
            #pragma unroll
            for (int nf = 0; nf < 8; nf++) {
                int col = bn + (wn << 6) + (nf << 3) + lc;
                float vx = c[mf][nf][2 * h]     + bias[col];
                float vy = c[mf][nf][2 * h + 1] + bias[col + 1];
                if (MODE == 2) {
                    vx = 0.5f * vx * (1.f + erff(vx * 0.70710678118654752f));
                    vy = 0.5f * vy * (1.f + erff(vy * 0.70710678118654752f));
                    __nv_bfloat16* Cb = (__nv_bfloat16*)C;
                    *(__nv_bfloat162*)&Cb[drow * (size_t)N + col] =
                        __floats2bfloat162_rn(vx, vy);
                } else if (MODE == 4 || MODE == 5) {
                    if (MODE == 5) {
                        vx *= 0.17677669529663687f;
                        vy *= 0.17677669529663687f;
                    }
                    __nv_bfloat16* Cb = (__nv_bfloat16*)C;
                    *(__nv_bfloat162*)&Cb[drow * (size_t)N + col] =
                        __floats2bfloat162_rn(vx, vy);
                } else if (MODE == 1) {
                    float2 e = *(const float2*)&extra[drow * 256 + col];
                    vx += e.x; vy += e.y;
                    *(float2*)&C[drow * 256 + col] = make_float2(vx, vy);
                } else if (MODE == 3) {
                    float2 e = *(const float2*)&extra[drow * 256 + col];
                    vx += e.x; vy += e.y;
                    *(float2*)&C[drow * (size_t)N + col] = make_float2(vx, vy);
                } else {
                    *(float2*)&C[drow * (size_t)N + col] = make_float2(vx, vy);
                }
            }
        }
    }
}

// ---------------- windowed attention -------------------------------------------
__global__ void __launch_bounds__(128)
attn_kernel(const __nv_bfloat16* __restrict__ q, const __nv_bfloat16* __restrict__ kv,
            const float* __restrict__ cmb, __nv_bfloat16* __restrict__ out) {
    __shared__ float ks[64][36];
    __shared__ float vs[64][36];
    __shared__ float cmbs[4096];
    int blk = blockIdx.x;
    int b_ = blk >> 3, head = blk & 7;
    int tid = threadIdx.x;
    int n = tid >> 1, half = tid & 1;
    int t0 = b_ << 6;
    int hoff = half << 4;
    int dbase = (head << 5) + hoff;

    {
        uint32_t cb = smem_u32(cmbs);
        const float* csrc = cmb + ((size_t)(((b_ & 255) << 3) + head) << 12);
        #pragma unroll
        for (int i = 0; i < 8; i++) {
            int id = tid + (i << 7);
            cp16(cb + id * 16, csrc + id * 4);
        }
        cp_commit();
    }

    const __nv_bfloat16* kvrow = kv + (size_t)(t0 + n) * 512 + dbase;
    #pragma unroll
    for (int j = 0; j < 2; j++) {
        uint4 uk = *(const uint4*)(kvrow + 8 * j);
        uint4 uv = *(const uint4*)(kvrow + 256 + 8 * j);
        const __nv_bfloat162* pk = (const __nv_bfloat162*)&uk;
        const __nv_bfloat162* pv = (const __nv_bfloat162*)&uv;
        #pragma unroll
        for (int i = 0; i < 4; i++) {
            float2 fk = __bfloat1622float2(pk[i]);
            float2 fv = __bfloat1622float2(pv[i]);
            ks[n][hoff + 8*j + 2*i]     = fk.x;
            ks[n][hoff + 8*j + 2*i + 1] = fk.y;
            vs[n][hoff + 8*j + 2*i]     = fv.x;
            vs[n][hoff + 8*j + 2*i + 1] = fv.y;
        }
    }
    float qr[16];
    const __nv_bfloat16* qrow = q + (size_t)(t0 + n) * 256 + dbase;
    #pragma unroll
    for (int j = 0; j < 2; j++) {
        uint4 uq = *(const uint4*)(qrow + 8 * j);
        const __nv_bfloat162* pq = (const __nv_bfloat162*)&uq;
        #pragma unroll
        for (int i = 0; i < 4; i++) {
            float2 f = __bfloat1622float2(pq[i]);
            qr[8*j + 2*i] = f.x; qr[8*j + 2*i + 1] = f.y;
        }
    }
    cp_wait0();
    __syncthreads();

    float accv[16];
    #pragma unroll
    for (int d = 0; d < 16; d++) accv[d] = 0.f;
    float sum = 0.f;
    #pragma unroll 1
    for (int mt = 0; mt < 64; mt += 16) {
        float e[16];
        #pragma unroll
        for (int i = 0; i < 16; i++) {
            int m = mt + i;
            float dp = 0.f;
            #pragma unroll
            for (int j4 = 0; j4 < 4; j4++) {
                float4 kf = *(const float4*)&ks[m][hoff + 4 * j4];
                dp += qr[4*j4+0]*kf.x + qr[4*j4+1]*kf.y + qr[4*j4+2]*kf.z + qr[4*j4+3]*kf.w;
            }
            float dot = dp + __shfl_xor_sync(~0u, dp, 1);
            e[i] = __expf(dot + cmbs[(m << 6) + n]);
        }
        #pragma unroll
        for (int i = 0; i < 16; i++) {
            int m = mt + i;
            sum += e[i];
            #pragma unroll
            for (int j4 = 0; j4 < 4; j4++) {
                float4 vf = *(const float4*)&vs[m][hoff + 4 * j4];
                accv[4*j4+0] += e[i] * vf.x; accv[4*j4+1] += e[i] * vf.y;
                accv[4*j4+2] += e[i] * vf.z; accv[4*j4+3] += e[i] * vf.w;
            }
        }
    }
    float inv = 1.f / sum;
    __nv_bfloat16* orow = out + (size_t)(t0 + n) * 256 + dbase;
    #pragma unroll
    for (int i = 0; i < 8; i++)
        *(__nv_bfloat162*)&orow[2 * i] =
            __floats2bfloat162_rn(accv[2*i] * inv, accv[2*i+1] * inv);
}

// ---------------- launch -------------------------------------------------------
extern "C" void kernel_launch(void* const* d_in, const int* in_sizes, int n_in,
                              void* d_out, int out_size) {
    (void)in_sizes; (void)n_in; (void)out_size;
    const float* ref  = (const float*)d_in[0];
    const float* adj  = (const float*)d_in[1];
    const float* mask = (const float*)d_in[2];
    const float* n1g = (const float*)d_in[5];
    const float* n1b = (const float*)d_in[6];
    const float* qw  = (const float*)d_in[7];
    const float* qb  = (const float*)d_in[8];
    const float* kvw = (const float*)d_in[9];
    const float* kvb = (const float*)d_in[10];
    const float* rel = (const float*)d_in[11];
    const float* pw  = (const float*)d_in[12];
    const float* pb  = (const float*)d_in[13];
    const float* n2g = (const float*)d_in[14];
    const float* n2b = (const float*)d_in[15];
    const float* f1w = (const float*)d_in[16];
    const float* f1b = (const float*)d_in[17];
    const float* f2w = (const float*)d_in[18];
    const float* f2b = (const float*)d_in[19];
    float* out = (float*)d_out;

    float *x, *cmb;
    __nv_bfloat16 *q, *kv, *rw, *aw, *ao, *l2, *h, *wt;
    cudaGetSymbolAddress((void**)&x,   g_x);
    cudaGetSymbolAddress((void**)&cmb, g_cmb);
    cudaGetSymbolAddress((void**)&q,   g_q);
    cudaGetSymbolAddress((void**)&kv,  g_kv);
    cudaGetSymbolAddress((void**)&rw,  g_rw);
    cudaGetSymbolAddress((void**)&aw,  g_aw);
    cudaGetSymbolAddress((void**)&ao,  g_ao);
    cudaGetSymbolAddress((void**)&l2,  g_l2);
    cudaGetSymbolAddress((void**)&h,   g_h);
    cudaGetSymbolAddress((void**)&wt,  g_wt);

    cudaFuncSetAttribute(gemm_mma<1>, cudaFuncAttributeMaxDynamicSharedMemorySize, GEMM_SMEM);
    cudaFuncSetAttribute(gemm_mma<2>, cudaFuncAttributeMaxDynamicSharedMemorySize, GEMM_SMEM);
    cudaFuncSetAttribute(gemm_mma<3>, cudaFuncAttributeMaxDynamicSharedMemorySize, GEMM_SMEM);
    cudaFuncSetAttribute(gemm_mma<4>, cudaFuncAttributeMaxDynamicSharedMemorySize, GEMM_SMEM);
    cudaFuncSetAttribute(gemm_mma<5>, cudaFuncAttributeMaxDynamicSharedMemorySize, GEMM_SMEM);

    prep_kernel<<<2816, dim3(32, 8)>>>(qw, kvw, pw, f1w, f2w, wt, rel, mask, cmb);
    ln1_kernel<<<TOK / 8, 256>>>(ref, adj, n1g, n1b);
    gemm_mma<5><<<dim3(2, 1024), 256, GEMM_SMEM>>>(rw, wt + WT_Q,  qb,  (float*)q,  256, 256,  nullptr);
    gemm_mma<4><<<dim3(4, 1024), 256, GEMM_SMEM>>>(aw, wt + WT_KV, kvb, (float*)kv, 256, 512,  nullptr);
    attn_kernel<<<16384, 128>>>(q, kv, cmb, ao);
    gemm_mma<1><<<dim3(2, 1024), 256, GEMM_SMEM>>>(ao, wt + WT_P,  pb,  x,  256, 256,  ref);
    ln2_kernel<<<TOK / 8, 256>>>(n2g, n2b);
    gemm_mma<2><<<dim3(8, 1024), 256, GEMM_SMEM>>>(l2, wt + WT_F1, f1b, (float*)h, 256, 1024, nullptr);
    gemm_mma<3><<<dim3(2, 1024), 256, GEMM_SMEM>>>(h,  wt + WT_F2, f2b, out, 1024, 256, x);
}